// round 14
// baseline (speedup 1.0000x reference)
#include <cuda_runtime.h>
#include <cuda_bf16.h>

// ---------------- problem constants ----------------
#define NND 100000
#define EED 1600000

// ---------------- device scratch ----------------
__device__ __align__(16) __nv_bfloat16 g_xh1b[(size_t)NND * 128]; // layer1 features, bf16
__device__ float g_as1[NND * 8];
__device__ float g_ad1[NND * 8];
__device__ float g_ae1p[(size_t)EED * 8];   // per-edge EDGE-ONLY attn terms (CSR order)
__device__ float2 g_meta[EED];              // {src_bits, ae2} (CSR order)
__device__ int   g_counts[NND];
__device__ int   g_rowoff[NND];
__device__ int   g_cursor[NND];
__device__ int   g_partials[256];
__device__ float g_xh2[NND * 16];
__device__ float g_as2[NND];
__device__ float g_ad2[NND];
__device__ float g_M1[128];
__device__ float g_M2[16];
__device__ int   g_is64;
__device__ int   g_scan_flag;

__device__ __forceinline__ int ld_idx(const void* ei, long long idx, int is64) {
    return is64 ? (int)((const long long*)ei)[idx] : ((const int*)ei)[idx];
}

__device__ __forceinline__ unsigned f2tf32(float f) {
    unsigned r;
    asm("cvt.rna.tf32.f32 %0, %1;" : "=r"(r) : "f"(f));
    return r;
}

__device__ __forceinline__ void mma_tf32(float* d, const unsigned* a, const unsigned* b) {
    asm volatile(
        "mma.sync.aligned.m16n8k8.row.col.f32.tf32.tf32.f32 "
        "{%0,%1,%2,%3}, {%4,%5,%6,%7}, {%8,%9}, {%0,%1,%2,%3};"
        : "+f"(d[0]), "+f"(d[1]), "+f"(d[2]), "+f"(d[3])
        : "r"(a[0]), "r"(a[1]), "r"(a[2]), "r"(a[3]), "r"(b[0]), "r"(b[1]));
}

// ---------------- fused init: detect dtype + zero counts + fold We + reset scan flag ----------------
__global__ void k_init(const unsigned* w, int n,
                       const float* __restrict__ We1, const float* __restrict__ ae1,
                       const float* __restrict__ We2, const float* __restrict__ ae2) {
    int i = blockIdx.x * blockDim.x + threadIdx.x;
    if (i < n) g_counts[i] = 0;
    if (blockIdx.x == 0) {
        int t = threadIdx.x;
        if (t == 0) {
            int is64 = 1;
            for (int j = 1; j < 256; j += 2)
                if (w[j] != 0u) { is64 = 0; break; }
            g_is64 = is64;
            g_scan_flag = 0;
        }
        if (t < 128) {
            int d = t >> 3, h = t & 7;
            float s = 0.f;
            #pragma unroll
            for (int c = 0; c < 16; c++) s += We1[d * 128 + h * 16 + c] * ae1[h * 16 + c];
            g_M1[d * 8 + h] = s;
        }
        if (t < 16) {
            float s = 0.f;
            #pragma unroll
            for (int c = 0; c < 16; c++) s += We2[t * 16 + c] * ae2[c];
            g_M2[t] = s;
        }
    }
}

// ---------------- degree count: fire-and-forget RED atomics ----------------
__global__ void k_count(const void* ei, int E) {
    int e0 = (blockIdx.x * blockDim.x + threadIdx.x) * 4;
    if (e0 >= E) return;
    int is64 = g_is64;
    #pragma unroll
    for (int j = 0; j < 4; j++) {
        int e = e0 + j;
        if (e < E) {
            int dst = ld_idx(ei, (long long)E + e, is64);
            atomicAdd(&g_counts[dst], 1);   // return discarded -> RED
        }
    }
}

// ---------------- scan1 + scan2 fused (last-block-done) ----------------
__global__ void k_scan12(int n, int nb) {
    __shared__ int sm[256];
    __shared__ int isLast;
    int i0 = blockIdx.x * 1024 + threadIdx.x * 4;
    int s = 0;
    #pragma unroll
    for (int j = 0; j < 4; j++) if (i0 + j < n) s += g_counts[i0 + j];
    sm[threadIdx.x] = s;
    __syncthreads();
    for (int off = 128; off; off >>= 1) {
        if (threadIdx.x < off) sm[threadIdx.x] += sm[threadIdx.x + off];
        __syncthreads();
    }
    if (threadIdx.x == 0) {
        g_partials[blockIdx.x] = sm[0];
        __threadfence();
        int done = atomicAdd(&g_scan_flag, 1);
        isLast = (done == gridDim.x - 1);
    }
    __syncthreads();
    if (!isLast) return;
    int t = threadIdx.x;
    __shared__ int sc[128];
    int v = 0;
    if (t < 128) {
        v = (t < nb) ? g_partials[t] : 0;
        sc[t] = v;
    }
    __syncthreads();
    for (int off = 1; off < 128; off <<= 1) {
        int x = 0;
        if (t < 128 && t >= off) x = sc[t - off];
        __syncthreads();
        if (t < 128) sc[t] += x;
        __syncthreads();
    }
    if (t < nb) g_partials[t] = sc[t] - v;   // exclusive
}

__global__ void k_scan3(int n) {
    __shared__ int sm[256];
    int base = g_partials[blockIdx.x];
    int i0 = blockIdx.x * 1024 + threadIdx.x * 4;
    int v[4];
    #pragma unroll
    for (int j = 0; j < 4; j++) v[j] = (i0 + j < n) ? g_counts[i0 + j] : 0;
    int e0 = 0, e1 = v[0], e2 = e1 + v[1], e3 = e2 + v[2];
    int tsum = e3 + v[3];
    sm[threadIdx.x] = tsum;
    __syncthreads();
    for (int off = 1; off < 256; off <<= 1) {
        int x = 0;
        if (threadIdx.x >= off) x = sm[threadIdx.x - off];
        __syncthreads();
        sm[threadIdx.x] += x;
        __syncthreads();
    }
    int toff = base + sm[threadIdx.x] - tsum;
    if (i0 + 0 < n) { g_rowoff[i0 + 0] = toff + e0; g_cursor[i0 + 0] = toff + e0; }
    if (i0 + 1 < n) { g_rowoff[i0 + 1] = toff + e1; g_cursor[i0 + 1] = toff + e1; }
    if (i0 + 2 < n) { g_rowoff[i0 + 2] = toff + e2; g_cursor[i0 + 2] = toff + e2; }
    if (i0 + 3 < n) { g_rowoff[i0 + 3] = toff + e3; g_cursor[i0 + 3] = toff + e3; }
}

// ---------------- fused: tf32 GEMM (blocks < ngemm) + edge-only scatter (blocks >= ngemm) ----------------
// Legal because scatter reads only M1/M2 + rowoff/cursor + inputs — nothing gemm writes.
#define AS_STRIDE 36
#define BS_STRIDE 136
__global__ __launch_bounds__(256, 2)
void k_gemm_scatter(const float* __restrict__ X, const float* __restrict__ W,
                    const float* __restrict__ atts1, const float* __restrict__ attd1,
                    int nrows, const void* ei, const float* __restrict__ eattr,
                    int E, int ngemm) {
    __shared__ unsigned As[128 * AS_STRIDE];   // [m][k], tf32 bits (gemm role)
    __shared__ unsigned Bs[32 * BS_STRIDE];    // [k][n], tf32 bits (gemm role)
    __shared__ float satts[128], sattd[128];   // gemm role
    __shared__ float M1s[128];                 // scatter role
    __shared__ float M2s[16];                  // scatter role
    int tid = threadIdx.x;

    if (blockIdx.x >= ngemm) {
        // ---- scatter role: edge-only attn terms into CSR ----
        if (tid < 128) M1s[tid] = g_M1[tid];
        if (tid < 16)  M2s[tid] = g_M2[tid];
        __syncthreads();
        int e = (blockIdx.x - ngemm) * 256 + tid;
        if (e >= E) return;
        int is64 = g_is64;
        int src = ld_idx(ei, e, is64);
        int dst = ld_idx(ei, (long long)E + e, is64);
        float ea[16];
        const float4* p = (const float4*)(eattr + (size_t)e * 16);
        *(float4*)&ea[0]  = __ldcs(p + 0);
        *(float4*)&ea[4]  = __ldcs(p + 1);
        *(float4*)&ea[8]  = __ldcs(p + 2);
        *(float4*)&ea[12] = __ldcs(p + 3);
        float4 alo = make_float4(0, 0, 0, 0), ahi = alo;
        float a2 = 0.f;
        #pragma unroll
        for (int d = 0; d < 16; d++) {
            float ev = ea[d];
            float4 mlo = *(const float4*)&M1s[d * 8];
            float4 mhi = *(const float4*)&M1s[d * 8 + 4];
            alo.x += ev * mlo.x; alo.y += ev * mlo.y; alo.z += ev * mlo.z; alo.w += ev * mlo.w;
            ahi.x += ev * mhi.x; ahi.y += ev * mhi.y; ahi.z += ev * mhi.z; ahi.w += ev * mhi.w;
            a2 += ev * M2s[d];
        }
        int pos = atomicAdd(&g_cursor[dst], 1);
        float* r = g_ae1p + (size_t)pos * 8;
        __stcs((float4*)r,       alo);
        __stcs((float4*)(r + 4), ahi);
        __stcs(&g_meta[pos], make_float2(__int_as_float(src), a2));
        return;
    }

    // ---- gemm role ----
    if (tid < 128) { satts[tid] = atts1[tid]; sattd[tid] = attd1[tid]; }
    int warp = tid >> 5, lane = tid & 31;
    int gid = lane >> 2, tig = lane & 3;
    int warpM = warp & 3, warpN = warp >> 2;
    int rowBase = blockIdx.x * 128;

    float acc[2][8][4];
    #pragma unroll
    for (int mi = 0; mi < 2; mi++)
        #pragma unroll
        for (int nj = 0; nj < 8; nj++)
            #pragma unroll
            for (int q = 0; q < 4; q++) acc[mi][nj][q] = 0.f;

    for (int kc = 0; kc < 4; kc++) {
        {   // A tile: 128 rows x 32 k
            int r = tid >> 1;
            int seg = (tid & 1) * 16;
            int grow = rowBase + r;
            float v[16];
            if (grow < nrows) {
                const float4* p = (const float4*)(X + (size_t)grow * 128 + kc * 32 + seg);
                #pragma unroll
                for (int j = 0; j < 4; j++) *(float4*)&v[j * 4] = __ldcs(p + j);
            } else {
                #pragma unroll
                for (int j = 0; j < 16; j++) v[j] = 0.f;
            }
            unsigned* dstp = As + r * AS_STRIDE + seg;
            #pragma unroll
            for (int j = 0; j < 16; j++) dstp[j] = f2tf32(v[j]);
        }
        {   // B tile: 32 k x 128 n
            int k = tid >> 3;
            int n0 = (tid & 7) * 16;
            const float4* p = (const float4*)(W + (size_t)(kc * 32 + k) * 128 + n0);
            float v[16];
            #pragma unroll
            for (int j = 0; j < 4; j++) *(float4*)&v[j * 4] = p[j];
            unsigned* dstp = Bs + k * BS_STRIDE + n0;
            #pragma unroll
            for (int j = 0; j < 16; j++) dstp[j] = f2tf32(v[j]);
        }
        __syncthreads();
        #pragma unroll
        for (int ks = 0; ks < 4; ks++) {
            int kk = ks * 8 + tig;
            unsigned a[2][4];
            #pragma unroll
            for (int mi = 0; mi < 2; mi++) {
                int rb = warpM * 32 + mi * 16 + gid;
                a[mi][0] = As[rb * AS_STRIDE + kk];
                a[mi][1] = As[(rb + 8) * AS_STRIDE + kk];
                a[mi][2] = As[rb * AS_STRIDE + kk + 4];
                a[mi][3] = As[(rb + 8) * AS_STRIDE + kk + 4];
            }
            unsigned b[8][2];
            #pragma unroll
            for (int nj = 0; nj < 8; nj++) {
                int nb = warpN * 64 + nj * 8 + gid;
                b[nj][0] = Bs[(ks * 8 + tig) * BS_STRIDE + nb];
                b[nj][1] = Bs[(ks * 8 + tig + 4) * BS_STRIDE + nb];
            }
            #pragma unroll
            for (int mi = 0; mi < 2; mi++)
                #pragma unroll
                for (int nj = 0; nj < 8; nj++)
                    mma_tf32(acc[mi][nj], a[mi], b[nj]);
        }
        __syncthreads();
    }

    // ---- epilogue: bf16 store of xh1 + fused a_s1/a_d1 ----
    #pragma unroll
    for (int mi = 0; mi < 2; mi++) {
        #pragma unroll
        for (int half = 0; half < 2; half++) {
            int grow = rowBase + warpM * 32 + mi * 16 + gid + half * 8;
            bool ok = grow < nrows;
            float pa[4] = {0.f, 0.f, 0.f, 0.f}, pd[4] = {0.f, 0.f, 0.f, 0.f};
            #pragma unroll
            for (int nj = 0; nj < 8; nj++) {
                float v0 = acc[mi][nj][half * 2 + 0];
                float v1 = acc[mi][nj][half * 2 + 1];
                int cb = warpN * 64 + nj * 8 + tig * 2;
                if (ok) {
                    __nv_bfloat162 bv = __floats2bfloat162_rn(v0, v1);
                    *(__nv_bfloat162*)(g_xh1b + (size_t)grow * 128 + cb) = bv;
                }
                int hl = nj >> 1;
                pa[hl] += v0 * satts[cb] + v1 * satts[cb + 1];
                pd[hl] += v0 * sattd[cb] + v1 * sattd[cb + 1];
            }
            #pragma unroll
            for (int off = 1; off <= 2; off <<= 1) {
                #pragma unroll
                for (int hl = 0; hl < 4; hl++) {
                    pa[hl] += __shfl_xor_sync(0xffffffffu, pa[hl], off);
                    pd[hl] += __shfl_xor_sync(0xffffffffu, pd[hl], off);
                }
            }
            if (tig == 0 && ok) {
                #pragma unroll
                for (int hl = 0; hl < 4; hl++) {
                    g_as1[grow * 8 + warpN * 4 + hl] = pa[hl];
                    g_ad1[grow * 8 + warpN * 4 + hl] = pd[hl];
                }
            }
        }
    }
}

// ---------------- layer-1 aggregation: z computed in-loop, online softmax, fused L2 lin ----------------
__global__ __launch_bounds__(256)
void k_agg1(const float* __restrict__ b1, const float* __restrict__ W2,
            const float* __restrict__ atts2, const float* __restrict__ attd2, int nnodes) {
    __shared__ float W2t[16 * 128];
    __shared__ float as2s[16], ad2s[16];
    int tid = threadIdx.x;
    {
        int k = tid & 127;
        for (int c = tid >> 7; c < 16; c += 2)
            W2t[c * 128 + k] = W2[k * 16 + c];
    }
    if (tid < 16) { as2s[tid] = atts2[tid]; ad2s[tid] = attd2[tid]; }
    __syncthreads();

    int warp = tid >> 5, lane = tid & 31;
    int n = blockIdx.x * 8 + warp;
    if (n >= nnodes) return;

    int h = lane >> 2;
    float adv = g_ad1[n * 8 + h];
    int start = g_rowoff[n], end = start + g_counts[n];

    float m = -1e30f, s = 0.f;
    float4 acc = make_float4(0, 0, 0, 0);
    int p = start;
    for (; p + 3 < end; p += 4) {
        float zv[4]; uint2 rv[4];
        #pragma unroll
        for (int u = 0; u < 4; u++) {
            float aev = g_ae1p[(size_t)(p + u) * 8 + h];
            int srcu = __float_as_int(g_meta[p + u].x);
            float asv = g_as1[srcu * 8 + h];
            rv[u] = *(const uint2*)(g_xh1b + (size_t)srcu * 128 + lane * 4);
            float z = asv + adv + aev;
            zv[u] = z > 0.f ? z : 0.2f * z;
        }
        float zm = fmaxf(fmaxf(zv[0], zv[1]), fmaxf(zv[2], zv[3]));
        float mN = fmaxf(m, zm);
        float sc = __expf(m - mN);
        s *= sc;
        acc.x *= sc; acc.y *= sc; acc.z *= sc; acc.w *= sc;
        #pragma unroll
        for (int u = 0; u < 4; u++) {
            float w = __expf(zv[u] - mN);
            s += w;
            float2 a0 = __bfloat1622float2(*(__nv_bfloat162*)&rv[u].x);
            float2 b0 = __bfloat1622float2(*(__nv_bfloat162*)&rv[u].y);
            acc.x += w * a0.x; acc.y += w * a0.y;
            acc.z += w * b0.x; acc.w += w * b0.y;
        }
        m = mN;
    }
    for (; p < end; p++) {
        float aev = g_ae1p[(size_t)p * 8 + h];
        int src0 = __float_as_int(g_meta[p].x);
        float asv = g_as1[src0 * 8 + h];
        uint2 r0 = *(const uint2*)(g_xh1b + (size_t)src0 * 128 + lane * 4);
        float z0 = asv + adv + aev;
        z0 = z0 > 0.f ? z0 : 0.2f * z0;
        float mN = fmaxf(m, z0);
        float sc = __expf(m - mN);
        float w0 = __expf(z0 - mN);
        s = s * sc + w0;
        float2 a0 = __bfloat1622float2(*(__nv_bfloat162*)&r0.x);
        float2 b0 = __bfloat1622float2(*(__nv_bfloat162*)&r0.y);
        acc.x = acc.x * sc + w0 * a0.x;
        acc.y = acc.y * sc + w0 * a0.y;
        acc.z = acc.z * sc + w0 * b0.x;
        acc.w = acc.w * sc + w0 * b0.y;
        m = mN;
    }
    float inv = 1.f / (s + 1e-16f);
    float4 bb = *(const float4*)(b1 + lane * 4);
    float h0 = acc.x * inv + bb.x;
    float h1v = acc.y * inv + bb.y;
    float h2 = acc.z * inv + bb.z;
    float h3 = acc.w * inv + bb.w;
    h0 = h0 > 0.f ? h0 : (__expf(h0) - 1.f);
    h1v = h1v > 0.f ? h1v : (__expf(h1v) - 1.f);
    h2 = h2 > 0.f ? h2 : (__expf(h2) - 1.f);
    h3 = h3 > 0.f ? h3 : (__expf(h3) - 1.f);

    float4 hv = make_float4(h0, h1v, h2, h3);
    float part[16];
    #pragma unroll
    for (int c = 0; c < 16; c++) {
        float4 wv = *(const float4*)&W2t[c * 128 + lane * 4];
        part[c] = hv.x * wv.x + hv.y * wv.y + hv.z * wv.z + hv.w * wv.w;
    }
    #pragma unroll
    for (int off = 16; off; off >>= 1) {
        #pragma unroll
        for (int c = 0; c < 16; c++)
            part[c] += __shfl_xor_sync(0xffffffffu, part[c], off);
    }
    if (lane == 0) {
        float4* o = (float4*)(g_xh2 + (size_t)n * 16);
        o[0] = make_float4(part[0], part[1], part[2], part[3]);
        o[1] = make_float4(part[4], part[5], part[6], part[7]);
        o[2] = make_float4(part[8], part[9], part[10], part[11]);
        o[3] = make_float4(part[12], part[13], part[14], part[15]);
        float as2 = 0.f, ad2 = 0.f;
        #pragma unroll
        for (int c = 0; c < 16; c++) { as2 += part[c] * as2s[c]; ad2 += part[c] * ad2s[c]; }
        g_as2[n] = as2;
        g_ad2[n] = ad2;
    }
}

// ---------------- layer-2 aggregation (online softmax) + bias + log_softmax ----------------
__global__ __launch_bounds__(256)
void k_agg2(const float* __restrict__ b2, float* __restrict__ out, int nnodes) {
    int tid = threadIdx.x, warp = tid >> 5, lane = tid & 31;
    int n = blockIdx.x * 8 + warp;
    if (n >= nnodes) return;
    float ad = g_ad2[n];
    int start = g_rowoff[n], end = start + g_counts[n];
    float m = -1e30f, s = 0.f, acc = 0.f;
    int p = start;
    for (; p + 3 < end; p += 4) {
        float zv[4], vv[4];
        #pragma unroll
        for (int u = 0; u < 4; u++) {
            float2 mt = g_meta[p + u];
            int srcu = __float_as_int(mt.x);
            float z = g_as2[srcu] + ad + mt.y;
            zv[u] = z > 0.f ? z : 0.2f * z;
            vv[u] = (lane < 16) ? g_xh2[(size_t)srcu * 16 + lane] : 0.f;
        }
        float zm = fmaxf(fmaxf(zv[0], zv[1]), fmaxf(zv[2], zv[3]));
        float mN = fmaxf(m, zm);
        float sc = __expf(m - mN);
        s *= sc; acc *= sc;
        #pragma unroll
        for (int u = 0; u < 4; u++) {
            float w = __expf(zv[u] - mN);
            s += w;
            acc += w * vv[u];
        }
        m = mN;
    }
    for (; p < end; p++) {
        float2 mt0 = g_meta[p];
        int src0 = __float_as_int(mt0.x);
        float z0 = g_as2[src0] + ad + mt0.y;
        z0 = z0 > 0.f ? z0 : 0.2f * z0;
        float v0 = (lane < 16) ? g_xh2[(size_t)src0 * 16 + lane] : 0.f;
        float mN = fmaxf(m, z0);
        float sc = __expf(m - mN);
        float w0 = __expf(z0 - mN);
        s = s * sc + w0;
        acc = acc * sc + w0 * v0;
        m = mN;
    }
    int c = lane & 15;
    float o = acc / (s + 1e-16f) + b2[c];
    float mx = o;
    #pragma unroll
    for (int off = 8; off; off >>= 1)
        mx = fmaxf(mx, __shfl_xor_sync(0xffffffffu, mx, off, 16));
    float ex = __expf(o - mx);
    float se = ex;
    #pragma unroll
    for (int off = 8; off; off >>= 1)
        se += __shfl_xor_sync(0xffffffffu, se, off, 16);
    float rres = o - mx - __logf(se);
    if (lane < 16) out[(size_t)n * 16 + lane] = rres;
}

// ---------------- launch ----------------
extern "C" void kernel_launch(void* const* d_in, const int* in_sizes, int n_in,
                              void* d_out, int out_size) {
    const float* x     = (const float*)d_in[0];
    const void*  ei    = d_in[1];
    const float* eattr = (const float*)d_in[2];
    const float* W1    = (const float*)d_in[3];
    const float* atts1 = (const float*)d_in[4];
    const float* attd1 = (const float*)d_in[5];
    const float* We1   = (const float*)d_in[6];
    const float* atte1 = (const float*)d_in[7];
    const float* b1    = (const float*)d_in[8];
    const float* W2    = (const float*)d_in[9];
    const float* atts2 = (const float*)d_in[10];
    const float* attd2 = (const float*)d_in[11];
    const float* We2   = (const float*)d_in[12];
    const float* atte2 = (const float*)d_in[13];
    const float* b2    = (const float*)d_in[14];
    float* out = (float*)d_out;

    int n = in_sizes[0] / 128;
    int E = in_sizes[1] / 2;
    int nb = (n + 1023) / 1024;
    int ngemm = (n + 127) / 128;
    int nscat = (E + 255) / 256;

    k_init<<<(n + 255) / 256, 256>>>((const unsigned*)ei, n, We1, atte1, We2, atte2);
    k_count<<<(E / 4 + 255) / 256, 256>>>(ei, E);
    k_scan12<<<nb, 256>>>(n, nb);
    k_scan3<<<nb, 256>>>(n);
    k_gemm_scatter<<<ngemm + nscat, 256>>>(x, W1, atts1, attd1, n, ei, eattr, E, ngemm);
    k_agg1<<<(n + 7) / 8, 256>>>(b1, W2, atts2, attd2, n);
    k_agg2<<<(n + 7) / 8, 256>>>(b2, out, n);
}

// round 15
// speedup vs baseline: 1.0489x; 1.0489x over previous
#include <cuda_runtime.h>
#include <cuda_bf16.h>

// ---------------- problem constants ----------------
#define NND 100000
#define EED 1600000

// ---------------- device scratch ----------------
__device__ __align__(16) __nv_bfloat16 g_xh1b[(size_t)NND * 128]; // layer1 features, bf16
__device__ float g_as1[NND * 8];
__device__ float g_ad1[NND * 8];
__device__ float g_z1[(size_t)EED * 8];     // per-edge leaky-relu'd logits (CSR order)
__device__ float2 g_meta[EED];              // {src_bits, ae2} (CSR order)
__device__ int   g_counts[NND];
__device__ int   g_rowoff[NND];
__device__ int   g_cursor[NND];
__device__ int   g_partials[256];
__device__ float g_xh2[NND * 16];
__device__ float g_as2[NND];
__device__ float g_ad2[NND];
__device__ float g_M1[128];
__device__ float g_M2[16];
__device__ int   g_is64;
__device__ int   g_scan_flag;

__device__ __forceinline__ int ld_idx(const void* ei, long long idx, int is64) {
    return is64 ? (int)((const long long*)ei)[idx] : ((const int*)ei)[idx];
}

__device__ __forceinline__ unsigned f2tf32(float f) {
    unsigned r;
    asm("cvt.rna.tf32.f32 %0, %1;" : "=r"(r) : "f"(f));
    return r;
}

__device__ __forceinline__ void mma_tf32(float* d, const unsigned* a, const unsigned* b) {
    asm volatile(
        "mma.sync.aligned.m16n8k8.row.col.f32.tf32.tf32.f32 "
        "{%0,%1,%2,%3}, {%4,%5,%6,%7}, {%8,%9}, {%0,%1,%2,%3};"
        : "+f"(d[0]), "+f"(d[1]), "+f"(d[2]), "+f"(d[3])
        : "r"(a[0]), "r"(a[1]), "r"(a[2]), "r"(a[3]), "r"(b[0]), "r"(b[1]));
}

// ---------------- fused init: detect dtype + zero counts + fold We + reset scan flag ----------------
__global__ void k_init(const unsigned* w, int n,
                       const float* __restrict__ We1, const float* __restrict__ ae1,
                       const float* __restrict__ We2, const float* __restrict__ ae2) {
    int i = blockIdx.x * blockDim.x + threadIdx.x;
    if (i < n) g_counts[i] = 0;
    if (blockIdx.x == 0) {
        int t = threadIdx.x;
        if (t == 0) {
            int is64 = 1;
            for (int j = 1; j < 256; j += 2)
                if (w[j] != 0u) { is64 = 0; break; }
            g_is64 = is64;
            g_scan_flag = 0;
        }
        if (t < 128) {
            int d = t >> 3, h = t & 7;
            float s = 0.f;
            #pragma unroll
            for (int c = 0; c < 16; c++) s += We1[d * 128 + h * 16 + c] * ae1[h * 16 + c];
            g_M1[d * 8 + h] = s;
        }
        if (t < 16) {
            float s = 0.f;
            #pragma unroll
            for (int c = 0; c < 16; c++) s += We2[t * 16 + c] * ae2[c];
            g_M2[t] = s;
        }
    }
}

// ---------------- fused: tf32 GEMM (blocks < ngemm) + degree count (blocks >= ngemm) ----------------
#define AS_STRIDE 36
#define BS_STRIDE 136
__global__ __launch_bounds__(256, 2)
void k_gemm_count(const float* __restrict__ X, const float* __restrict__ W,
                  const float* __restrict__ atts1, const float* __restrict__ attd1,
                  int nrows, const void* ei, int E, int ngemm) {
    __shared__ unsigned As[128 * AS_STRIDE];   // [m][k], tf32 bits
    __shared__ unsigned Bs[32 * BS_STRIDE];    // [k][n], tf32 bits
    __shared__ float satts[128], sattd[128];
    int tid = threadIdx.x;

    if (blockIdx.x >= ngemm) {
        // ---- count role: fire-and-forget RED atomics (occupancy-insensitive) ----
        int cb = blockIdx.x - ngemm;
        int e0 = (cb * 256 + tid) * 4;
        if (e0 < E) {
            int is64 = g_is64;
            #pragma unroll
            for (int j = 0; j < 4; j++) {
                int e = e0 + j;
                if (e < E) {
                    int dst = ld_idx(ei, (long long)E + e, is64);
                    atomicAdd(&g_counts[dst], 1);   // return discarded -> RED
                }
            }
        }
        return;
    }

    // ---- gemm role ----
    if (tid < 128) { satts[tid] = atts1[tid]; sattd[tid] = attd1[tid]; }
    int warp = tid >> 5, lane = tid & 31;
    int gid = lane >> 2, tig = lane & 3;
    int warpM = warp & 3, warpN = warp >> 2;
    int rowBase = blockIdx.x * 128;

    int arow = tid >> 1;
    int aseg = (tid & 1) * 16;
    int agrow = rowBase + arow;
    bool aok = agrow < nrows;
    const float* abase = X + (size_t)agrow * 128 + aseg;

    float acc[2][8][4];
    #pragma unroll
    for (int mi = 0; mi < 2; mi++)
        #pragma unroll
        for (int nj = 0; nj < 8; nj++)
            #pragma unroll
            for (int q = 0; q < 4; q++) acc[mi][nj][q] = 0.f;

    // preload A chunk 0 into registers
    float va[16];
    if (aok) {
        const float4* p = (const float4*)abase;
        #pragma unroll
        for (int j = 0; j < 4; j++) *(float4*)&va[j * 4] = __ldcs(p + j);
    } else {
        #pragma unroll
        for (int j = 0; j < 16; j++) va[j] = 0.f;
    }

    for (int kc = 0; kc < 4; kc++) {
        {   // A tile: store prefetched registers
            unsigned* dstp = As + arow * AS_STRIDE + aseg;
            #pragma unroll
            for (int j = 0; j < 16; j++) dstp[j] = f2tf32(va[j]);
        }
        {   // B tile: 32 k x 128 n (L2-hot, not prefetched)
            int k = tid >> 3;
            int n0 = (tid & 7) * 16;
            const float4* p = (const float4*)(W + (size_t)(kc * 32 + k) * 128 + n0);
            float v[16];
            #pragma unroll
            for (int j = 0; j < 4; j++) *(float4*)&v[j * 4] = p[j];
            unsigned* dstp = Bs + k * BS_STRIDE + n0;
            #pragma unroll
            for (int j = 0; j < 16; j++) dstp[j] = f2tf32(v[j]);
        }
        __syncthreads();
        // prefetch NEXT A chunk (va registers are dead after the smem store)
        if (kc < 3) {
            if (aok) {
                const float4* p = (const float4*)(abase + (kc + 1) * 32);
                #pragma unroll
                for (int j = 0; j < 4; j++) *(float4*)&va[j * 4] = __ldcs(p + j);
            }
        }
        #pragma unroll
        for (int ks = 0; ks < 4; ks++) {
            int kk = ks * 8 + tig;
            unsigned a[2][4];
            #pragma unroll
            for (int mi = 0; mi < 2; mi++) {
                int rb = warpM * 32 + mi * 16 + gid;
                a[mi][0] = As[rb * AS_STRIDE + kk];
                a[mi][1] = As[(rb + 8) * AS_STRIDE + kk];
                a[mi][2] = As[rb * AS_STRIDE + kk + 4];
                a[mi][3] = As[(rb + 8) * AS_STRIDE + kk + 4];
            }
            unsigned b[8][2];
            #pragma unroll
            for (int nj = 0; nj < 8; nj++) {
                int nb = warpN * 64 + nj * 8 + gid;
                b[nj][0] = Bs[(ks * 8 + tig) * BS_STRIDE + nb];
                b[nj][1] = Bs[(ks * 8 + tig + 4) * BS_STRIDE + nb];
            }
            #pragma unroll
            for (int mi = 0; mi < 2; mi++)
                #pragma unroll
                for (int nj = 0; nj < 8; nj++)
                    mma_tf32(acc[mi][nj], a[mi], b[nj]);
        }
        __syncthreads();
    }

    // ---- epilogue: bf16 store of xh1 + fused a_s1/a_d1 ----
    #pragma unroll
    for (int mi = 0; mi < 2; mi++) {
        #pragma unroll
        for (int half = 0; half < 2; half++) {
            int grow = rowBase + warpM * 32 + mi * 16 + gid + half * 8;
            bool ok = grow < nrows;
            float pa[4] = {0.f, 0.f, 0.f, 0.f}, pd[4] = {0.f, 0.f, 0.f, 0.f};
            #pragma unroll
            for (int nj = 0; nj < 8; nj++) {
                float v0 = acc[mi][nj][half * 2 + 0];
                float v1 = acc[mi][nj][half * 2 + 1];
                int cb = warpN * 64 + nj * 8 + tig * 2;
                if (ok) {
                    __nv_bfloat162 bv = __floats2bfloat162_rn(v0, v1);
                    *(__nv_bfloat162*)(g_xh1b + (size_t)grow * 128 + cb) = bv;
                }
                int hl = nj >> 1;
                pa[hl] += v0 * satts[cb] + v1 * satts[cb + 1];
                pd[hl] += v0 * sattd[cb] + v1 * sattd[cb + 1];
            }
            #pragma unroll
            for (int off = 1; off <= 2; off <<= 1) {
                #pragma unroll
                for (int hl = 0; hl < 4; hl++) {
                    pa[hl] += __shfl_xor_sync(0xffffffffu, pa[hl], off);
                    pd[hl] += __shfl_xor_sync(0xffffffffu, pd[hl], off);
                }
            }
            if (tig == 0 && ok) {
                #pragma unroll
                for (int hl = 0; hl < 4; hl++) {
                    g_as1[grow * 8 + warpN * 4 + hl] = pa[hl];
                    g_ad1[grow * 8 + warpN * 4 + hl] = pd[hl];
                }
            }
        }
    }
}

// ---------------- scan1 + scan2 fused (last-block-done) ----------------
__global__ void k_scan12(int n, int nb) {
    __shared__ int sm[256];
    __shared__ int isLast;
    int i0 = blockIdx.x * 1024 + threadIdx.x * 4;
    int s = 0;
    #pragma unroll
    for (int j = 0; j < 4; j++) if (i0 + j < n) s += g_counts[i0 + j];
    sm[threadIdx.x] = s;
    __syncthreads();
    for (int off = 128; off; off >>= 1) {
        if (threadIdx.x < off) sm[threadIdx.x] += sm[threadIdx.x + off];
        __syncthreads();
    }
    if (threadIdx.x == 0) {
        g_partials[blockIdx.x] = sm[0];
        __threadfence();
        int done = atomicAdd(&g_scan_flag, 1);
        isLast = (done == gridDim.x - 1);
    }
    __syncthreads();
    if (!isLast) return;
    int t = threadIdx.x;
    __shared__ int sc[128];
    int v = 0;
    if (t < 128) {
        v = (t < nb) ? g_partials[t] : 0;
        sc[t] = v;
    }
    __syncthreads();
    for (int off = 1; off < 128; off <<= 1) {
        int x = 0;
        if (t < 128 && t >= off) x = sc[t - off];
        __syncthreads();
        if (t < 128) sc[t] += x;
        __syncthreads();
    }
    if (t < nb) g_partials[t] = sc[t] - v;   // exclusive
}

__global__ void k_scan3(int n) {
    __shared__ int sm[256];
    int base = g_partials[blockIdx.x];
    int i0 = blockIdx.x * 1024 + threadIdx.x * 4;
    int v[4];
    #pragma unroll
    for (int j = 0; j < 4; j++) v[j] = (i0 + j < n) ? g_counts[i0 + j] : 0;
    int e0 = 0, e1 = v[0], e2 = e1 + v[1], e3 = e2 + v[2];
    int tsum = e3 + v[3];
    sm[threadIdx.x] = tsum;
    __syncthreads();
    for (int off = 1; off < 256; off <<= 1) {
        int x = 0;
        if (threadIdx.x >= off) x = sm[threadIdx.x - off];
        __syncthreads();
        sm[threadIdx.x] += x;
        __syncthreads();
    }
    int toff = base + sm[threadIdx.x] - tsum;
    if (i0 + 0 < n) { g_rowoff[i0 + 0] = toff + e0; g_cursor[i0 + 0] = toff + e0; }
    if (i0 + 1 < n) { g_rowoff[i0 + 1] = toff + e1; g_cursor[i0 + 1] = toff + e1; }
    if (i0 + 2 < n) { g_rowoff[i0 + 2] = toff + e2; g_cursor[i0 + 2] = toff + e2; }
    if (i0 + 3 < n) { g_rowoff[i0 + 3] = toff + e3; g_cursor[i0 + 3] = toff + e3; }
}

// ---------------- scatter: build CSR z-records + meta (standalone, high occupancy) ----------------
__global__ void k_scatter(const void* ei, const float* __restrict__ eattr, int E) {
    __shared__ float M1s[128];
    __shared__ float M2s[16];
    int t = threadIdx.x;
    if (t < 128) M1s[t] = g_M1[t];
    if (t < 16)  M2s[t] = g_M2[t];
    __syncthreads();
    int e = blockIdx.x * 256 + t;
    if (e >= E) return;
    int is64 = g_is64;
    int src = ld_idx(ei, e, is64);
    int dst = ld_idx(ei, (long long)E + e, is64);
    float ea[16];
    const float4* p = (const float4*)(eattr + (size_t)e * 16);
    *(float4*)&ea[0]  = __ldcs(p + 0);
    *(float4*)&ea[4]  = __ldcs(p + 1);
    *(float4*)&ea[8]  = __ldcs(p + 2);
    *(float4*)&ea[12] = __ldcs(p + 3);
    float4 alo = make_float4(0, 0, 0, 0), ahi = alo;
    float a2 = 0.f;
    #pragma unroll
    for (int d = 0; d < 16; d++) {
        float ev = ea[d];
        float4 mlo = *(const float4*)&M1s[d * 8];
        float4 mhi = *(const float4*)&M1s[d * 8 + 4];
        alo.x += ev * mlo.x; alo.y += ev * mlo.y; alo.z += ev * mlo.z; alo.w += ev * mlo.w;
        ahi.x += ev * mhi.x; ahi.y += ev * mhi.y; ahi.z += ev * mhi.z; ahi.w += ev * mhi.w;
        a2 += ev * M2s[d];
    }
    float4 s0 = *(const float4*)(g_as1 + (size_t)src * 8);
    float4 s1 = *(const float4*)(g_as1 + (size_t)src * 8 + 4);
    float4 d0 = *(const float4*)(g_ad1 + (size_t)dst * 8);
    float4 d1 = *(const float4*)(g_ad1 + (size_t)dst * 8 + 4);
    float z[8];
    z[0] = s0.x + d0.x + alo.x; z[1] = s0.y + d0.y + alo.y;
    z[2] = s0.z + d0.z + alo.z; z[3] = s0.w + d0.w + alo.w;
    z[4] = s1.x + d1.x + ahi.x; z[5] = s1.y + d1.y + ahi.y;
    z[6] = s1.z + d1.z + ahi.z; z[7] = s1.w + d1.w + ahi.w;
    #pragma unroll
    for (int h = 0; h < 8; h++) z[h] = z[h] > 0.f ? z[h] : 0.2f * z[h];

    int pos = atomicAdd(&g_cursor[dst], 1);
    float* r = g_z1 + (size_t)pos * 8;
    __stcs((float4*)r,       make_float4(z[0], z[1], z[2], z[3]));
    __stcs((float4*)(r + 4), make_float4(z[4], z[5], z[6], z[7]));
    __stcs(&g_meta[pos], make_float2(__int_as_float(src), a2));
}

// ---------------- layer-1 aggregation (online softmax), bf16 gather, fused layer-2 lin ----------------
__global__ __launch_bounds__(256)
void k_agg1(const float* __restrict__ b1, const float* __restrict__ W2,
            const float* __restrict__ atts2, const float* __restrict__ attd2, int nnodes) {
    __shared__ float W2t[16 * 128];
    __shared__ float as2s[16], ad2s[16];
    int tid = threadIdx.x;
    {
        int k = tid & 127;
        for (int c = tid >> 7; c < 16; c += 2)
            W2t[c * 128 + k] = W2[k * 16 + c];
    }
    if (tid < 16) { as2s[tid] = atts2[tid]; ad2s[tid] = attd2[tid]; }
    __syncthreads();

    int warp = tid >> 5, lane = tid & 31;
    int n = blockIdx.x * 8 + warp;
    if (n >= nnodes) return;

    int h = lane >> 2;
    int start = g_rowoff[n], end = start + g_counts[n];

    float m = -1e30f, s = 0.f;
    float4 acc = make_float4(0, 0, 0, 0);
    int p = start;
    for (; p + 3 < end; p += 4) {
        float zv[4]; uint2 rv[4];
        #pragma unroll
        for (int u = 0; u < 4; u++) {
            zv[u] = g_z1[(size_t)(p + u) * 8 + h];
            int srcu = __float_as_int(g_meta[p + u].x);
            rv[u] = *(const uint2*)(g_xh1b + (size_t)srcu * 128 + lane * 4);
        }
        float zm = fmaxf(fmaxf(zv[0], zv[1]), fmaxf(zv[2], zv[3]));
        float mN = fmaxf(m, zm);
        float sc = __expf(m - mN);
        s *= sc;
        acc.x *= sc; acc.y *= sc; acc.z *= sc; acc.w *= sc;
        #pragma unroll
        for (int u = 0; u < 4; u++) {
            float w = __expf(zv[u] - mN);
            s += w;
            float2 a0 = __bfloat1622float2(*(__nv_bfloat162*)&rv[u].x);
            float2 b0 = __bfloat1622float2(*(__nv_bfloat162*)&rv[u].y);
            acc.x += w * a0.x; acc.y += w * a0.y;
            acc.z += w * b0.x; acc.w += w * b0.y;
        }
        m = mN;
    }
    for (; p < end; p++) {
        float z0 = g_z1[(size_t)p * 8 + h];
        int src0 = __float_as_int(g_meta[p].x);
        uint2 r0 = *(const uint2*)(g_xh1b + (size_t)src0 * 128 + lane * 4);
        float mN = fmaxf(m, z0);
        float sc = __expf(m - mN);
        float w0 = __expf(z0 - mN);
        s = s * sc + w0;
        float2 a0 = __bfloat1622float2(*(__nv_bfloat162*)&r0.x);
        float2 b0 = __bfloat1622float2(*(__nv_bfloat162*)&r0.y);
        acc.x = acc.x * sc + w0 * a0.x;
        acc.y = acc.y * sc + w0 * a0.y;
        acc.z = acc.z * sc + w0 * b0.x;
        acc.w = acc.w * sc + w0 * b0.y;
        m = mN;
    }
    float inv = 1.f / (s + 1e-16f);
    float4 bb = *(const float4*)(b1 + lane * 4);
    float h0 = acc.x * inv + bb.x;
    float h1v = acc.y * inv + bb.y;
    float h2 = acc.z * inv + bb.z;
    float h3 = acc.w * inv + bb.w;
    h0 = h0 > 0.f ? h0 : (__expf(h0) - 1.f);
    h1v = h1v > 0.f ? h1v : (__expf(h1v) - 1.f);
    h2 = h2 > 0.f ? h2 : (__expf(h2) - 1.f);
    h3 = h3 > 0.f ? h3 : (__expf(h3) - 1.f);

    float4 hv = make_float4(h0, h1v, h2, h3);
    float part[16];
    #pragma unroll
    for (int c = 0; c < 16; c++) {
        float4 wv = *(const float4*)&W2t[c * 128 + lane * 4];
        part[c] = hv.x * wv.x + hv.y * wv.y + hv.z * wv.z + hv.w * wv.w;
    }
    #pragma unroll
    for (int off = 16; off; off >>= 1) {
        #pragma unroll
        for (int c = 0; c < 16; c++)
            part[c] += __shfl_xor_sync(0xffffffffu, part[c], off);
    }
    if (lane == 0) {
        float4* o = (float4*)(g_xh2 + (size_t)n * 16);
        o[0] = make_float4(part[0], part[1], part[2], part[3]);
        o[1] = make_float4(part[4], part[5], part[6], part[7]);
        o[2] = make_float4(part[8], part[9], part[10], part[11]);
        o[3] = make_float4(part[12], part[13], part[14], part[15]);
        float as2 = 0.f, ad2 = 0.f;
        #pragma unroll
        for (int c = 0; c < 16; c++) { as2 += part[c] * as2s[c]; ad2 += part[c] * ad2s[c]; }
        g_as2[n] = as2;
        g_ad2[n] = ad2;
    }
}

// ---------------- layer-2 aggregation (online softmax) + bias + log_softmax ----------------
__global__ __launch_bounds__(256)
void k_agg2(const float* __restrict__ b2, float* __restrict__ out, int nnodes) {
    int tid = threadIdx.x, warp = tid >> 5, lane = tid & 31;
    int n = blockIdx.x * 8 + warp;
    if (n >= nnodes) return;
    float ad = g_ad2[n];
    int start = g_rowoff[n], end = start + g_counts[n];
    float m = -1e30f, s = 0.f, acc = 0.f;
    int p = start;
    for (; p + 3 < end; p += 4) {
        float zv[4], vv[4];
        #pragma unroll
        for (int u = 0; u < 4; u++) {
            float2 mt = g_meta[p + u];
            int srcu = __float_as_int(mt.x);
            float z = g_as2[srcu] + ad + mt.y;
            zv[u] = z > 0.f ? z : 0.2f * z;
            vv[u] = (lane < 16) ? g_xh2[(size_t)srcu * 16 + lane] : 0.f;
        }
        float zm = fmaxf(fmaxf(zv[0], zv[1]), fmaxf(zv[2], zv[3]));
        float mN = fmaxf(m, zm);
        float sc = __expf(m - mN);
        s *= sc; acc *= sc;
        #pragma unroll
        for (int u = 0; u < 4; u++) {
            float w = __expf(zv[u] - mN);
            s += w;
            acc += w * vv[u];
        }
        m = mN;
    }
    for (; p < end; p++) {
        float2 mt0 = g_meta[p];
        int src0 = __float_as_int(mt0.x);
        float z0 = g_as2[src0] + ad + mt0.y;
        z0 = z0 > 0.f ? z0 : 0.2f * z0;
        float v0 = (lane < 16) ? g_xh2[(size_t)src0 * 16 + lane] : 0.f;
        float mN = fmaxf(m, z0);
        float sc = __expf(m - mN);
        float w0 = __expf(z0 - mN);
        s = s * sc + w0;
        acc = acc * sc + w0 * v0;
        m = mN;
    }
    int c = lane & 15;
    float o = acc / (s + 1e-16f) + b2[c];
    float mx = o;
    #pragma unroll
    for (int off = 8; off; off >>= 1)
        mx = fmaxf(mx, __shfl_xor_sync(0xffffffffu, mx, off, 16));
    float ex = __expf(o - mx);
    float se = ex;
    #pragma unroll
    for (int off = 8; off; off >>= 1)
        se += __shfl_xor_sync(0xffffffffu, se, off, 16);
    float rres = o - mx - __logf(se);
    if (lane < 16) out[(size_t)n * 16 + lane] = rres;
}

// ---------------- launch ----------------
extern "C" void kernel_launch(void* const* d_in, const int* in_sizes, int n_in,
                              void* d_out, int out_size) {
    const float* x     = (const float*)d_in[0];
    const void*  ei    = d_in[1];
    const float* eattr = (const float*)d_in[2];
    const float* W1    = (const float*)d_in[3];
    const float* atts1 = (const float*)d_in[4];
    const float* attd1 = (const float*)d_in[5];
    const float* We1   = (const float*)d_in[6];
    const float* atte1 = (const float*)d_in[7];
    const float* b1    = (const float*)d_in[8];
    const float* W2    = (const float*)d_in[9];
    const float* atts2 = (const float*)d_in[10];
    const float* attd2 = (const float*)d_in[11];
    const float* We2   = (const float*)d_in[12];
    const float* atte2 = (const float*)d_in[13];
    const float* b2    = (const float*)d_in[14];
    float* out = (float*)d_out;

    int n = in_sizes[0] / 128;
    int E = in_sizes[1] / 2;
    int nb = (n + 1023) / 1024;
    int ngemm = (n + 127) / 128;
    int ncount = (E / 4 + 255) / 256;

    k_init<<<(n + 255) / 256, 256>>>((const unsigned*)ei, n, We1, atte1, We2, atte2);
    k_gemm_count<<<ngemm + ncount, 256>>>(x, W1, atts1, attd1, n, ei, E, ngemm);
    k_scan12<<<nb, 256>>>(n, nb);
    k_scan3<<<nb, 256>>>(n);
    k_scatter<<<(E + 255) / 256, 256>>>(ei, eattr, E);
    k_agg1<<<(n + 7) / 8, 256>>>(b1, W2, atts2, attd2, n);
    k_agg2<<<(n + 7) / 8, 256>>>(b2, out, n);
}